// round 14
// baseline (speedup 1.0000x reference)
#include <cuda_runtime.h>
#include <cstdint>

// Problem dims
constexpr int kS = 96;
constexpr int kB = 16;
constexpr int kD = 512;
constexpr int kH = 128;
constexpr int kRows = kS * kB;   // 1536

constexpr int kSplit = 3;        // uneven K-split: 192/160/160

// Per-K-split partials; pairwise sums them on the fly.
__device__ float g_part[kSplit][2][kRows * kH];   // 4.7 MB

// ---------------------------------------------------------------------------
// GEMM via tf32 mma.sync.m16n8k8.
// BM=32, BN=128, BK=32/stage, 256 threads = 8 warps (2 m x 4 n),
// warp tile 16m x 32n. Double-buffered smem (46 KB -> 2 blocks/SM).
// grid (48, 2, 3) = 288 blocks ~= 2 co-resident per SM.
// smem stride 36 (= 4 mod 32): frag addresses 4*gid+tig hit all 32 banks.
// ---------------------------------------------------------------------------
constexpr int AS_STRIDE = 36;
constexpr int BS_STRIDE = 36;
constexpr int AS_SZ = 32 * AS_STRIDE;    // 1152
constexpr int BS_SZ = 128 * BS_STRIDE;   // 4608
constexpr int GEMM_SMEM = 2 * (AS_SZ + BS_SZ) * 4;   // 46080 B

__device__ __forceinline__ uint32_t f2tf32(float x) {
    uint32_t r;
    asm("cvt.rna.tf32.f32 %0, %1;" : "=r"(r) : "f"(x));
    return r;
}

__device__ __forceinline__ void mma_tf32(
    float& c0, float& c1, float& c2, float& c3,
    uint32_t a0, uint32_t a1, uint32_t a2, uint32_t a3,
    uint32_t b0, uint32_t b1)
{
    asm volatile(
        "mma.sync.aligned.m16n8k8.row.col.f32.tf32.tf32.f32 "
        "{%0,%1,%2,%3}, {%4,%5,%6,%7}, {%8,%9}, {%0,%1,%2,%3};"
        : "+f"(c0), "+f"(c1), "+f"(c2), "+f"(c3)
        : "r"(a0), "r"(a1), "r"(a2), "r"(a3), "r"(b0), "r"(b1));
}

__global__ __launch_bounds__(256) void gemm1_kernel(
    const float* __restrict__ embeds, const float* __restrict__ embeds_cmp,
    const float* __restrict__ W1)
{
    extern __shared__ float sm[];
    uint32_t* As = (uint32_t*)sm;                 // [2][32][36]
    uint32_t* Bs = (uint32_t*)(sm + 2 * AS_SZ);   // [2][128][36]

    const int which = blockIdx.y;
    const int z     = blockIdx.z;
    const float* src = which ? embeds_cmp : embeds;
    const int wcol = which ? kD : 0;
    float* dst = g_part[z][which];
    const int row0 = blockIdx.x * 32;

    // Uneven split: stage counts 6/5/5 of BK=32, starts 0/192/352
    const int kbeg  = (z == 0) ? 0 : (z == 1 ? 192 : 352);
    const int nIter = (z == 0) ? 6 : 5;

    const int tid  = threadIdx.x;
    const int wid  = tid >> 5;
    const int lane = tid & 31;
    const int gid  = lane >> 2;     // 0..7
    const int tig  = lane & 3;      // 0..3
    const int warp_m = wid & 1;     // 2 m-warps (16 rows each)
    const int warp_n = wid >> 1;    // 4 n-warps (32 cols each)

    const int a_m0 = tid >> 3;      // 0..31
    const int a_k4 = tid & 7;       // 0..7

    float4 pa, pb[4];
    float acc[4][4] = {};           // [n-tile][c0..c3]

    auto load_tiles = [&](int k0) {
        pa = *(const float4*)&src[(row0 + a_m0) * kD + k0 + a_k4 * 4];
        #pragma unroll
        for (int t = 0; t < 4; t++) {
            int h = a_m0 + t * 32;
            pb[t] = *(const float4*)&W1[h * (2 * kD) + wcol + k0 + a_k4 * 4];
        }
    };
    auto store_tiles = [&](int buf) {
        uint32_t* A = As + buf * AS_SZ;
        uint32_t* B = Bs + buf * BS_SZ;
        {
            uint32_t* p = &A[a_m0 * AS_STRIDE + a_k4 * 4];
            p[0] = f2tf32(pa.x);
            p[1] = f2tf32(pa.y);
            p[2] = f2tf32(pa.z);
            p[3] = f2tf32(pa.w);
        }
        #pragma unroll
        for (int t = 0; t < 4; t++) {
            int h = a_m0 + t * 32;
            uint32_t* p = &B[h * BS_STRIDE + a_k4 * 4];
            p[0] = f2tf32(pb[t].x);
            p[1] = f2tf32(pb[t].y);
            p[2] = f2tf32(pb[t].z);
            p[3] = f2tf32(pb[t].w);
        }
    };
    auto compute = [&](int buf) {
        const uint32_t* A = As + buf * AS_SZ;
        const uint32_t* B = Bs + buf * BS_SZ;
        #pragma unroll
        for (int kk8 = 0; kk8 < 4; kk8++) {
            const int kb = kk8 * 8;
            uint32_t af[4];
            {
                int rbase = warp_m * 16;
                const uint32_t* ap = &A[(rbase + gid) * AS_STRIDE + kb + tig];
                af[0] = ap[0];
                af[1] = ap[8 * AS_STRIDE];
                af[2] = ap[4];
                af[3] = ap[8 * AS_STRIDE + 4];
            }
            uint32_t bf[4][2];
            #pragma unroll
            for (int n = 0; n < 4; n++) {
                int nb = warp_n * 32 + n * 8;
                const uint32_t* bp = &B[(nb + gid) * BS_STRIDE + kb + tig];
                bf[n][0] = bp[0];
                bf[n][1] = bp[4];
            }
            #pragma unroll
            for (int n = 0; n < 4; n++)
                mma_tf32(acc[n][0], acc[n][1], acc[n][2], acc[n][3],
                         af[0], af[1], af[2], af[3], bf[n][0], bf[n][1]);
        }
    };

    int buf = 0;
    load_tiles(kbeg);
    store_tiles(0);
    __syncthreads();
    for (int it = 1; it < nIter; it++) {
        load_tiles(kbeg + it * 32);
        compute(buf);
        store_tiles(buf ^ 1);
        __syncthreads();
        buf ^= 1;
    }
    compute(buf);

    // Epilogue: c0/c1 -> (row, 2*tig), c2/c3 -> (row+8, 2*tig)
    {
        int r0 = row0 + warp_m * 16 + gid;
        #pragma unroll
        for (int n = 0; n < 4; n++) {
            int c = warp_n * 32 + n * 8 + 2 * tig;
            *(float2*)&dst[r0 * kH + c]       = make_float2(acc[n][0], acc[n][1]);
            *(float2*)&dst[(r0 + 8) * kH + c] = make_float2(acc[n][2], acc[n][3]);
        }
    }
}

// ---------------------------------------------------------------------------
// Pairwise + fused 3-partial reduction, h-split across two warpgroups.
// Block = 16 i x 32 j x one b, 512 threads:
//   warps 0-7  accumulate h in [0,64)
//   warps 8-15 accumulate h in [64,128)
// then smem exchange + add. grid (6, 3, 16) = 288 blocks, 31 warps/SM.
// ---------------------------------------------------------------------------
__global__ __launch_bounds__(512) void pairwise_kernel(
    const float* __restrict__ b1, const float* __restrict__ W2,
    const float* __restrict__ b2, float* __restrict__ out)
{
    __shared__ float hb_s[32 * 132];
    __shared__ float ha_s[16 * 128];
    __shared__ float w2_s[256];
    __shared__ float4 xch[256];

    const int b  = blockIdx.z;
    const int i0 = blockIdx.x * 16;
    const int j0 = blockIdx.y * 32;
    const int tid = threadIdx.x;

    // hb tile (32 j-rows x 128 h), summing 3 partials: 1024 float4 / 512 thr
    #pragma unroll
    for (int t = 0; t < 2; t++) {
        int idx = tid + t * 512;
        int j = idx >> 5, h4 = idx & 31;
        int off = ((j0 + j) * kB + b) * kH + h4 * 4;
        float4 v0 = *(const float4*)&g_part[0][1][off];
        float4 v1 = *(const float4*)&g_part[1][1][off];
        float4 v2 = *(const float4*)&g_part[2][1][off];
        float4 s;
        s.x = v0.x + v1.x + v2.x;  s.y = v0.y + v1.y + v2.y;
        s.z = v0.z + v1.z + v2.z;  s.w = v0.w + v1.w + v2.w;
        *(float4*)&hb_s[j * 132 + h4 * 4] = s;
    }
    // ha tile (16 i-rows x 128 h), 3 partials + b1: 512 float4 / 512 thr
    {
        int i = tid >> 5, h4 = tid & 31;
        int off = ((i0 + i) * kB + b) * kH + h4 * 4;
        float4 s  = *(const float4*)&b1[h4 * 4];
        float4 v0 = *(const float4*)&g_part[0][0][off];
        float4 v1 = *(const float4*)&g_part[1][0][off];
        float4 v2 = *(const float4*)&g_part[2][0][off];
        s.x += v0.x + v1.x + v2.x;  s.y += v0.y + v1.y + v2.y;
        s.z += v0.z + v1.z + v2.z;  s.w += v0.w + v1.w + v2.w;
        *(float4*)&ha_s[i * 128 + h4 * 4] = s;
    }
    if (tid < 256) w2_s[tid] = W2[tid];
    const float bias0 = b2[0];
    const float bias1 = b2[1];
    __syncthreads();

    const int lane = tid & 31;          // j lane
    const int w    = (tid >> 5) & 7;    // i-pair within half
    const int hh   = tid >> 8;          // h-half: 0 or 1
    const int hofs = hh * 64;

    const float* hap0 = &ha_s[(w * 2 + 0) * 128 + hofs];
    const float* hap1 = &ha_s[(w * 2 + 1) * 128 + hofs];
    const float* hbp  = &hb_s[lane * 132 + hofs];
    const float* w2a  = &w2_s[hofs];
    const float* w2b  = &w2_s[128 + hofs];

    float acc00 = 0.f, acc01 = 0.f, acc10 = 0.f, acc11 = 0.f;

    #pragma unroll
    for (int h4 = 0; h4 < 16; h4++) {
        float4 hv = *(const float4*)&hbp[h4 * 4];          // lane-distinct
        float4 a0 = *(const float4*)&hap0[h4 * 4];         // broadcast
        float4 a1 = *(const float4*)&hap1[h4 * 4];         // broadcast
        float4 w0 = *(const float4*)&w2a[h4 * 4];          // broadcast
        float4 w1 = *(const float4*)&w2b[h4 * 4];          // broadcast

        float u0 = fmaxf(a0.x + hv.x, 0.f);
        float u1 = fmaxf(a0.y + hv.y, 0.f);
        float u2 = fmaxf(a0.z + hv.z, 0.f);
        float u3 = fmaxf(a0.w + hv.w, 0.f);
        acc00 = fmaf(u0, w0.x, acc00);  acc01 = fmaf(u0, w1.x, acc01);
        acc00 = fmaf(u1, w0.y, acc00);  acc01 = fmaf(u1, w1.y, acc01);
        acc00 = fmaf(u2, w0.z, acc00);  acc01 = fmaf(u2, w1.z, acc01);
        acc00 = fmaf(u3, w0.w, acc00);  acc01 = fmaf(u3, w1.w, acc01);

        float t0 = fmaxf(a1.x + hv.x, 0.f);
        float t1 = fmaxf(a1.y + hv.y, 0.f);
        float t2 = fmaxf(a1.z + hv.z, 0.f);
        float t3 = fmaxf(a1.w + hv.w, 0.f);
        acc10 = fmaf(t0, w0.x, acc10);  acc11 = fmaf(t0, w1.x, acc11);
        acc10 = fmaf(t1, w0.y, acc10);  acc11 = fmaf(t1, w1.y, acc11);
        acc10 = fmaf(t2, w0.z, acc10);  acc11 = fmaf(t2, w1.z, acc11);
        acc10 = fmaf(t3, w0.w, acc10);  acc11 = fmaf(t3, w1.w, acc11);
    }

    // Combine the two h-halves: upper half publishes, lower half adds+writes.
    if (hh == 1)
        xch[tid & 255] = make_float4(acc00, acc01, acc10, acc11);
    __syncthreads();
    if (hh == 0) {
        float4 o = xch[tid];
        const int i = i0 + w * 2;
        const int j = j0 + lane;
        size_t o0 = ((size_t)(i * kS + j) * kB + b) * 2;
        size_t o1 = ((size_t)((i + 1) * kS + j) * kB + b) * 2;
        *(float2*)&out[o0] = make_float2(acc00 + o.x + bias0, acc01 + o.y + bias1);
        *(float2*)&out[o1] = make_float2(acc10 + o.z + bias0, acc11 + o.w + bias1);
    }
}

// ---------------------------------------------------------------------------
// Input order: embeds, umask, qmask, embeds_cmp, W1, b1, W2, b2
// ---------------------------------------------------------------------------
extern "C" void kernel_launch(void* const* d_in, const int* in_sizes, int n_in,
                              void* d_out, int out_size)
{
    const float* embeds     = (const float*)d_in[0];
    const float* embeds_cmp = (const float*)d_in[3];
    const float* W1         = (const float*)d_in[4];
    const float* b1         = (const float*)d_in[5];
    const float* W2         = (const float*)d_in[6];
    const float* b2         = (const float*)d_in[7];
    float* out = (float*)d_out;

    cudaFuncSetAttribute(gemm1_kernel,
                         cudaFuncAttributeMaxDynamicSharedMemorySize, GEMM_SMEM);

    gemm1_kernel<<<dim3(48, 2, kSplit), 256, GEMM_SMEM>>>(embeds, embeds_cmp, W1);
    pairwise_kernel<<<dim3(6, 3, 16), 512>>>(b1, W2, b2, out);
}

// round 15
// speedup vs baseline: 1.6110x; 1.6110x over previous
#include <cuda_runtime.h>
#include <cstdint>

// Problem dims
constexpr int kS = 96;
constexpr int kB = 16;
constexpr int kD = 512;
constexpr int kH = 128;
constexpr int kRows = kS * kB;   // 1536

constexpr int kSplit = 3;        // uneven K-split: 192/160/160

// Per-K-split partials; pairwise sums them on the fly.
__device__ float g_part[kSplit][2][kRows * kH];   // 4.7 MB

// ---------------------------------------------------------------------------
// GEMM via tf32 mma.sync.m16n8k8.
// BM=64, BN=64, BK=32/stage, 256 threads = 8 warps (4 m-warps x 2 n-warps),
// warp tile 16m x 32n. Double-buffered smem (36.9 KB -> 2-3 blocks/SM).
// grid (24, 4, 3) = 288 blocks: blockIdx.y = which + 2*nhalf.
// smem stride 36 (= 4 mod 32): frag addresses 4*gid+tig hit all 32 banks.
// ---------------------------------------------------------------------------
constexpr int AS_STRIDE = 36;
constexpr int BS_STRIDE = 36;
constexpr int AS_SZ = 64 * AS_STRIDE;    // 2304
constexpr int BS_SZ = 64 * BS_STRIDE;    // 2304
constexpr int GEMM_SMEM = 2 * (AS_SZ + BS_SZ) * 4;   // 36864 B

__device__ __forceinline__ uint32_t f2tf32(float x) {
    uint32_t r;
    asm("cvt.rna.tf32.f32 %0, %1;" : "=r"(r) : "f"(x));
    return r;
}

__device__ __forceinline__ void mma_tf32(
    float& c0, float& c1, float& c2, float& c3,
    uint32_t a0, uint32_t a1, uint32_t a2, uint32_t a3,
    uint32_t b0, uint32_t b1)
{
    asm volatile(
        "mma.sync.aligned.m16n8k8.row.col.f32.tf32.tf32.f32 "
        "{%0,%1,%2,%3}, {%4,%5,%6,%7}, {%8,%9}, {%0,%1,%2,%3};"
        : "+f"(c0), "+f"(c1), "+f"(c2), "+f"(c3)
        : "r"(a0), "r"(a1), "r"(a2), "r"(a3), "r"(b0), "r"(b1));
}

__global__ __launch_bounds__(256) void gemm1_kernel(
    const float* __restrict__ embeds, const float* __restrict__ embeds_cmp,
    const float* __restrict__ W1)
{
    extern __shared__ float sm[];
    uint32_t* As = (uint32_t*)sm;                 // [2][64][36]
    uint32_t* Bs = (uint32_t*)(sm + 2 * AS_SZ);   // [2][64][36]

    const int which = blockIdx.y & 1;
    const int nhalf = blockIdx.y >> 1;
    const int z     = blockIdx.z;
    const float* src = which ? embeds_cmp : embeds;
    const int wcol = which ? kD : 0;
    const int h0   = nhalf * 64;
    float* dst = g_part[z][which];
    const int row0 = blockIdx.x * 64;

    // Uneven split: stage counts 6/5/5 of BK=32, starts 0/192/352
    const int kbeg  = (z == 0) ? 0 : (z == 1 ? 192 : 352);
    const int nIter = (z == 0) ? 6 : 5;

    const int tid  = threadIdx.x;
    const int wid  = tid >> 5;
    const int lane = tid & 31;
    const int gid  = lane >> 2;     // 0..7
    const int tig  = lane & 3;      // 0..3
    const int warp_m = wid & 3;     // 4 m-warps (16 rows each)
    const int warp_n = wid >> 2;    // 2 n-warps (32 cols each)

    const int a_m0 = tid >> 3;      // 0..31
    const int a_k4 = tid & 7;       // 0..7

    float4 pa[2], pb[2];
    float acc[4][4] = {};           // [n-tile][c0..c3]

    auto load_tiles = [&](int k0) {
        #pragma unroll
        for (int t = 0; t < 2; t++) {
            int m = a_m0 + t * 32;
            pa[t] = *(const float4*)&src[(row0 + m) * kD + k0 + a_k4 * 4];
        }
        #pragma unroll
        for (int t = 0; t < 2; t++) {
            int h = h0 + a_m0 + t * 32;
            pb[t] = *(const float4*)&W1[h * (2 * kD) + wcol + k0 + a_k4 * 4];
        }
    };
    auto store_tiles = [&](int buf) {
        uint32_t* A = As + buf * AS_SZ;
        uint32_t* B = Bs + buf * BS_SZ;
        #pragma unroll
        for (int t = 0; t < 2; t++) {
            int m = a_m0 + t * 32;
            uint32_t* p = &A[m * AS_STRIDE + a_k4 * 4];
            p[0] = f2tf32(pa[t].x);
            p[1] = f2tf32(pa[t].y);
            p[2] = f2tf32(pa[t].z);
            p[3] = f2tf32(pa[t].w);
        }
        #pragma unroll
        for (int t = 0; t < 2; t++) {
            int h = a_m0 + t * 32;
            uint32_t* p = &B[h * BS_STRIDE + a_k4 * 4];
            p[0] = f2tf32(pb[t].x);
            p[1] = f2tf32(pb[t].y);
            p[2] = f2tf32(pb[t].z);
            p[3] = f2tf32(pb[t].w);
        }
    };
    auto compute = [&](int buf) {
        const uint32_t* A = As + buf * AS_SZ;
        const uint32_t* B = Bs + buf * BS_SZ;
        #pragma unroll
        for (int kk8 = 0; kk8 < 4; kk8++) {
            const int kb = kk8 * 8;
            uint32_t af[4];
            {
                int rbase = warp_m * 16;
                const uint32_t* ap = &A[(rbase + gid) * AS_STRIDE + kb + tig];
                af[0] = ap[0];
                af[1] = ap[8 * AS_STRIDE];
                af[2] = ap[4];
                af[3] = ap[8 * AS_STRIDE + 4];
            }
            uint32_t bf[4][2];
            #pragma unroll
            for (int n = 0; n < 4; n++) {
                int nb = warp_n * 32 + n * 8;
                const uint32_t* bp = &B[(nb + gid) * BS_STRIDE + kb + tig];
                bf[n][0] = bp[0];
                bf[n][1] = bp[4];
            }
            #pragma unroll
            for (int n = 0; n < 4; n++)
                mma_tf32(acc[n][0], acc[n][1], acc[n][2], acc[n][3],
                         af[0], af[1], af[2], af[3], bf[n][0], bf[n][1]);
        }
    };

    int buf = 0;
    load_tiles(kbeg);
    store_tiles(0);
    __syncthreads();
    for (int it = 1; it < nIter; it++) {
        load_tiles(kbeg + it * 32);
        compute(buf);
        store_tiles(buf ^ 1);
        __syncthreads();
        buf ^= 1;
    }
    compute(buf);

    // Epilogue: c0/c1 -> (row, 2*tig), c2/c3 -> (row+8, 2*tig)
    {
        int r0 = row0 + warp_m * 16 + gid;
        #pragma unroll
        for (int n = 0; n < 4; n++) {
            int c = h0 + warp_n * 32 + n * 8 + 2 * tig;
            *(float2*)&dst[r0 * kH + c]       = make_float2(acc[n][0], acc[n][1]);
            *(float2*)&dst[(r0 + 8) * kH + c] = make_float2(acc[n][2], acc[n][3]);
        }
    }
}

// ---------------------------------------------------------------------------
// Packed f32x2 helpers (sm_10x): halve fma-pipe instruction count.
// ---------------------------------------------------------------------------
using u64t = unsigned long long;

__device__ __forceinline__ u64t add2(u64t a, u64t b) {
    u64t r;
    asm("add.rn.f32x2 %0, %1, %2;" : "=l"(r) : "l"(a), "l"(b));
    return r;
}
__device__ __forceinline__ u64t fma2(u64t a, u64t b, u64t c) {
    u64t r;
    asm("fma.rn.f32x2 %0, %1, %2, %3;" : "=l"(r) : "l"(a), "l"(b), "l"(c));
    return r;
}
__device__ __forceinline__ u64t max2z(u64t a) {
    u64t r;
    asm("{\n\t.reg .f32 lo, hi;\n\t"
        "mov.b64 {lo, hi}, %1;\n\t"
        "max.f32 lo, lo, 0f00000000;\n\t"
        "max.f32 hi, hi, 0f00000000;\n\t"
        "mov.b64 %0, {lo, hi};\n\t}"
        : "=l"(r) : "l"(a));
    return r;
}
__device__ __forceinline__ float hsum2(u64t p) {
    float lo, hi;
    asm("mov.b64 {%0, %1}, %2;" : "=f"(lo), "=f"(hi) : "l"(p));
    return lo + hi;
}

// ---------------------------------------------------------------------------
// Pairwise + fused 3-partial reduction (R12 structure, f32x2 inner loop).
// Block = 16 i x 32 j x one b; each warp owns 2 i-rows, lane = j.
// grid (6, 3, 16) = 288 blocks, 256 threads.
// ---------------------------------------------------------------------------
__global__ __launch_bounds__(256) void pairwise_kernel(
    const float* __restrict__ b1, const float* __restrict__ W2,
    const float* __restrict__ b2, float* __restrict__ out)
{
    __shared__ float hb_s[32 * 132];
    __shared__ float ha_s[16 * 128];
    __shared__ float w2_s[256];

    const int b  = blockIdx.z;
    const int i0 = blockIdx.x * 16;
    const int j0 = blockIdx.y * 32;
    const int tid = threadIdx.x;

    #pragma unroll
    for (int t = 0; t < 4; t++) {
        int idx = tid + t * 256;
        int j = idx >> 5, h4 = idx & 31;
        int off = ((j0 + j) * kB + b) * kH + h4 * 4;
        float4 v0 = *(const float4*)&g_part[0][1][off];
        float4 v1 = *(const float4*)&g_part[1][1][off];
        float4 v2 = *(const float4*)&g_part[2][1][off];
        float4 s;
        s.x = v0.x + v1.x + v2.x;  s.y = v0.y + v1.y + v2.y;
        s.z = v0.z + v1.z + v2.z;  s.w = v0.w + v1.w + v2.w;
        *(float4*)&hb_s[j * 132 + h4 * 4] = s;
    }
    #pragma unroll
    for (int t = 0; t < 2; t++) {
        int idx = tid + t * 256;
        int i = idx >> 5, h4 = idx & 31;
        int off = ((i0 + i) * kB + b) * kH + h4 * 4;
        float4 s  = *(const float4*)&b1[h4 * 4];
        float4 v0 = *(const float4*)&g_part[0][0][off];
        float4 v1 = *(const float4*)&g_part[1][0][off];
        float4 v2 = *(const float4*)&g_part[2][0][off];
        s.x += v0.x + v1.x + v2.x;  s.y += v0.y + v1.y + v2.y;
        s.z += v0.z + v1.z + v2.z;  s.w += v0.w + v1.w + v2.w;
        *(float4*)&ha_s[i * 128 + h4 * 4] = s;
    }
    w2_s[tid] = W2[tid];
    const float bias0 = b2[0];
    const float bias1 = b2[1];
    __syncthreads();

    const int lane = tid & 31;
    const int w    = tid >> 5;
    const float* hap0 = &ha_s[(w * 2 + 0) * 128];
    const float* hap1 = &ha_s[(w * 2 + 1) * 128];
    const float* hbp  = &hb_s[lane * 132];

    u64t p00 = 0, p01 = 0, p10 = 0, p11 = 0;   // packed accumulators

    #pragma unroll 8
    for (int h4 = 0; h4 < 32; h4++) {
        ulonglong2 hv = *(const ulonglong2*)&hbp[h4 * 4];          // lane-distinct
        ulonglong2 a0 = *(const ulonglong2*)&hap0[h4 * 4];         // broadcast
        ulonglong2 a1 = *(const ulonglong2*)&hap1[h4 * 4];         // broadcast
        ulonglong2 w0 = *(const ulonglong2*)&w2_s[h4 * 4];         // broadcast (c=0)
        ulonglong2 w1 = *(const ulonglong2*)&w2_s[128 + h4 * 4];   // broadcast (c=1)

        u64t u01 = max2z(add2(a0.x, hv.x));
        u64t u23 = max2z(add2(a0.y, hv.y));
        p00 = fma2(u01, w0.x, p00);  p00 = fma2(u23, w0.y, p00);
        p01 = fma2(u01, w1.x, p01);  p01 = fma2(u23, w1.y, p01);

        u64t t01 = max2z(add2(a1.x, hv.x));
        u64t t23 = max2z(add2(a1.y, hv.y));
        p10 = fma2(t01, w0.x, p10);  p10 = fma2(t23, w0.y, p10);
        p11 = fma2(t01, w1.x, p11);  p11 = fma2(t23, w1.y, p11);
    }

    const int i  = i0 + w * 2;
    const int j  = j0 + lane;
    size_t o0 = ((size_t)(i * kS + j) * kB + b) * 2;
    size_t o1 = ((size_t)((i + 1) * kS + j) * kB + b) * 2;
    *(float2*)&out[o0] = make_float2(hsum2(p00) + bias0, hsum2(p01) + bias1);
    *(float2*)&out[o1] = make_float2(hsum2(p10) + bias0, hsum2(p11) + bias1);
}

// ---------------------------------------------------------------------------
// Input order: embeds, umask, qmask, embeds_cmp, W1, b1, W2, b2
// ---------------------------------------------------------------------------
extern "C" void kernel_launch(void* const* d_in, const int* in_sizes, int n_in,
                              void* d_out, int out_size)
{
    const float* embeds     = (const float*)d_in[0];
    const float* embeds_cmp = (const float*)d_in[3];
    const float* W1         = (const float*)d_in[4];
    const float* b1         = (const float*)d_in[5];
    const float* W2         = (const float*)d_in[6];
    const float* b2         = (const float*)d_in[7];
    float* out = (float*)d_out;

    cudaFuncSetAttribute(gemm1_kernel,
                         cudaFuncAttributeMaxDynamicSharedMemorySize, GEMM_SMEM);

    gemm1_kernel<<<dim3(24, 4, kSplit), 256, GEMM_SMEM>>>(embeds, embeds_cmp, W1);
    pairwise_kernel<<<dim3(6, 3, 16), 256>>>(b1, W2, b2, out);
}